// round 14
// baseline (speedup 1.0000x reference)
#include <cuda_runtime.h>
#include <cuda_bf16.h>
#include <cstdint>
#include <math.h>

#define BB 8
#define SS 1024
#define DD 512
#define HH 8
#define WW 8
#define DKK 64
#define SP2 1040   // S + 2*WIDTH
#define DD2 1024   // 2*D

// GEMM tiling: STAGES=3 double-barrier (R9-proven shape), KCH=32
#define STAGES 3
#define KCH 32
#define ROWSTRIDE 36                          // 32 + 4 pad floats
#define STAGE_FLOATS (128 * ROWSTRIDE)
#define STAGE_BYTES  (STAGE_FLOATS * 4)       // 18432
#define SMEM_SZ (2 * STAGES * STAGE_BYTES)    // 110592 B  (x2 CTAs = 221184 <= 227KB)

// attention tiling
#define SBLK 128
#define AROWS (SBLK + 18)                    // 146
#define ATTN_SMEM (2 * AROWS * 64 * 4)       // 74752 B

// ---------------- scratch ----------------
__device__ float g_newin[(size_t)BB * SP2 * DD];
__device__ float g_qkv[(size_t)BB * SP2 * 3072];   // [row][side*1536 + {q,k,v}*512 + d]
__device__ float g_attn[2 * (size_t)BB * SS * DD];
__device__ float g_x[2 * (size_t)BB * SS * DD];
__device__ float g_xb[2 * (size_t)BB * SS * DD];
// transposed weights [N][K], tf32-rounded
__device__ float g_qkvWt[2 * 3 * DD * DD];
__device__ float g_opWt[2 * DD * DD];
__device__ float g_hwWt[2 * 2 * DD2 * DD];
__device__ float g_qkvb[2 * 3 * DD];

// ---------------- helpers ----------------
__device__ __forceinline__ uint32_t smem_u32(const void* p) {
    uint32_t a;
    asm("{ .reg .u64 t; cvta.to.shared.u64 t, %1; cvt.u32.u64 %0, t; }" : "=r"(a) : "l"(p));
    return a;
}
__device__ __forceinline__ void cpa16(uint32_t dst, const void* src) {
    asm volatile("cp.async.cg.shared.global [%0], [%1], 16;" :: "r"(dst), "l"(src));
}
__device__ __forceinline__ void mma_tf32(float* d, const uint32_t* a, const uint32_t* b) {
    asm volatile(
        "mma.sync.aligned.m16n8k8.row.col.f32.tf32.tf32.f32 "
        "{%0,%1,%2,%3}, {%4,%5,%6,%7}, {%8,%9}, {%0,%1,%2,%3};"
        : "+f"(d[0]), "+f"(d[1]), "+f"(d[2]), "+f"(d[3])
        : "r"(a[0]), "r"(a[1]), "r"(a[2]), "r"(a[3]), "r"(b[0]), "r"(b[1]));
}

#define GEMM_PRE()                                                        \
    extern __shared__ float smf[];                                        \
    float* smA = smf;                                                     \
    float* smB = smf + STAGES * STAGE_FLOATS;                             \
    const int tid = threadIdx.x;                                          \
    const int wid = tid >> 5;                                             \
    const int lane = tid & 31;                                            \
    const int warp_m = wid & 3;                                           \
    const int warp_n = wid >> 2;                                          \
    const int m0 = blockIdx.y * 128;                                      \
    const uint32_t sbA = smem_u32(smA);                                   \
    const uint32_t sbB = smem_u32(smB);                                   \
    const int ldrow = tid >> 1;                                           \
    const int ldseg = (tid & 1) * 8;                                      \
    const uint32_t daBase = sbA + (uint32_t)(ldrow * ROWSTRIDE + ldseg) * 4; \
    const uint32_t dbBase = sbB + (uint32_t)(ldrow * ROWSTRIDE + ldseg) * 4;

// each chunk = 32 K-floats per row: thread covers segs {ldseg, ldseg+4, ldseg+16, ldseg+20}
#define ISSUE(c) do {                                                   \
        int _sl = (c) % STAGES;                                         \
        uint32_t _da = daBase + _sl * STAGE_BYTES;                      \
        uint32_t _db = dbBase + _sl * STAGE_BYTES;                      \
        const float* _ag = agp + (c) * KCH;                             \
        const float* _bg = bgp + (c) * KCH;                             \
        cpa16(_da,      _ag);                                           \
        cpa16(_da + 16, _ag + 4);                                       \
        cpa16(_da + 64, _ag + 16);                                      \
        cpa16(_da + 80, _ag + 20);                                      \
        cpa16(_db,      _bg);                                           \
        cpa16(_db + 16, _bg + 4);                                       \
        cpa16(_db + 64, _bg + 16);                                      \
        cpa16(_db + 80, _bg + 20);                                      \
        asm volatile("cp.async.commit_group;" ::: "memory");            \
    } while (0)

// R9-proven double-barrier mainloop (STAGES=3, prefetch distance 2)
#define MAINLOOP(...)                                                     \
    ISSUE(0); ISSUE(1);                                                   \
    for (int c = 0; c < nch; c++) {                                       \
        if (c + 2 < nch) { ISSUE(c + 2); }                                \
        else { asm volatile("cp.async.commit_group;" ::: "memory"); }     \
        asm volatile("cp.async.wait_group 2;" ::: "memory");              \
        __syncthreads();                                                  \
        const int sl = c % STAGES;                                        \
        const float* As = smA + sl * STAGE_FLOATS;                        \
        const float* Bs = smB + sl * STAGE_FLOATS;                        \
        __VA_ARGS__                                                       \
        __syncthreads();                                                  \
    }

// ============ GEMM 1: generic C = A @ Bt^T + bias (128x128 tile) ============
__global__ void __launch_bounds__(256, 2)
k_tgemm(const float* __restrict__ A, const float* __restrict__ Bt,
        const float* __restrict__ bias, float* __restrict__ C,
        int M, int N, int K)
{
    GEMM_PRE();
    const int n0 = blockIdx.x * 128;
    const int nch = K / KCH;
    const float* agp = A  + (size_t)(m0 + ldrow) * K + ldseg;
    const float* bgp = Bt + (size_t)(n0 + ldrow) * K + ldseg;

    float acc[2][8][4];
#pragma unroll
    for (int mi = 0; mi < 2; mi++)
#pragma unroll
        for (int ni = 0; ni < 8; ni++)
#pragma unroll
            for (int j = 0; j < 4; j++) acc[mi][ni][j] = 0.f;

    MAINLOOP(
#pragma unroll
        for (int s = 0; s < 4; s++) {
            const int cc = s * 8 + (lane & 3);
            uint32_t afr[2][4];
#pragma unroll
            for (int mi = 0; mi < 2; mi++) {
                const int r = warp_m * 32 + mi * 16 + (lane >> 2);
                afr[mi][0] = __float_as_uint(As[r * ROWSTRIDE + cc]);
                afr[mi][1] = __float_as_uint(As[(r + 8) * ROWSTRIDE + cc]);
                afr[mi][2] = __float_as_uint(As[r * ROWSTRIDE + cc + 4]);
                afr[mi][3] = __float_as_uint(As[(r + 8) * ROWSTRIDE + cc + 4]);
            }
            uint32_t bfr[8][2];
#pragma unroll
            for (int ni = 0; ni < 8; ni++) {
                const int n = warp_n * 64 + ni * 8 + (lane >> 2);
                bfr[ni][0] = __float_as_uint(Bs[n * ROWSTRIDE + cc]);
                bfr[ni][1] = __float_as_uint(Bs[n * ROWSTRIDE + cc + 4]);
            }
#pragma unroll
            for (int mi = 0; mi < 2; mi++)
#pragma unroll
                for (int ni = 0; ni < 8; ni++)
                    mma_tf32(acc[mi][ni], afr[mi], bfr[ni]);
        }
    )

#pragma unroll
    for (int mi = 0; mi < 2; mi++) {
        const int r = m0 + warp_m * 32 + mi * 16 + (lane >> 2);
#pragma unroll
        for (int ni = 0; ni < 8; ni++) {
            const int n = n0 + warp_n * 64 + ni * 8 + 2 * (lane & 3);
            const float b0 = bias[n], b1 = bias[n + 1];
            *(float2*)(C + (size_t)r * N + n) = make_float2(acc[mi][ni][0] + b0, acc[mi][ni][1] + b1);
            *(float2*)(C + (size_t)(r + 8) * N + n) = make_float2(acc[mi][ni][2] + b0, acc[mi][ni][3] + b1);
        }
    }
}

// ============ GEMM 2: out-proj + fused relative add, side-batched ============
__global__ void __launch_bounds__(256, 2)
k_opgemm(const float* __restrict__ lw, const float* __restrict__ rw,
         const float* __restrict__ lb3, const float* __restrict__ rb3,
         int M, int N, int K)
{
    GEMM_PRE();
    const int n0 = blockIdx.x * 128;
    const int side = blockIdx.z;
    const int nch = K / KCH;
    const float* A  = g_attn + (size_t)side * M * K;
    const float* Bt = g_opWt + (size_t)side * DD * DD;
    const float* bias = (side ? rb3 : lb3);
    const float* relw = side ? rw : lw;
    float* C = g_x + (size_t)side * M * N;

    const float* agp = A  + (size_t)(m0 + ldrow) * K + ldseg;
    const float* bgp = Bt + (size_t)(n0 + ldrow) * K + ldseg;

    float acc[2][8][4];
#pragma unroll
    for (int mi = 0; mi < 2; mi++)
#pragma unroll
        for (int ni = 0; ni < 8; ni++)
#pragma unroll
            for (int j = 0; j < 4; j++) acc[mi][ni][j] = 0.f;

    MAINLOOP(
#pragma unroll
        for (int s = 0; s < 4; s++) {
            const int cc = s * 8 + (lane & 3);
            uint32_t afr[2][4];
#pragma unroll
            for (int mi = 0; mi < 2; mi++) {
                const int r = warp_m * 32 + mi * 16 + (lane >> 2);
                afr[mi][0] = __float_as_uint(As[r * ROWSTRIDE + cc]);
                afr[mi][1] = __float_as_uint(As[(r + 8) * ROWSTRIDE + cc]);
                afr[mi][2] = __float_as_uint(As[r * ROWSTRIDE + cc + 4]);
                afr[mi][3] = __float_as_uint(As[(r + 8) * ROWSTRIDE + cc + 4]);
            }
            uint32_t bfr[8][2];
#pragma unroll
            for (int ni = 0; ni < 8; ni++) {
                const int n = warp_n * 64 + ni * 8 + (lane >> 2);
                bfr[ni][0] = __float_as_uint(Bs[n * ROWSTRIDE + cc]);
                bfr[ni][1] = __float_as_uint(Bs[n * ROWSTRIDE + cc + 4]);
            }
#pragma unroll
            for (int mi = 0; mi < 2; mi++)
#pragma unroll
                for (int ni = 0; ni < 8; ni++)
                    mma_tf32(acc[mi][ni], afr[mi], bfr[ni]);
        }
    )

    float wv[WW + 1];
#pragma unroll
    for (int j = 0; j <= WW; j++) wv[j] = relw[j];

#pragma unroll
    for (int mi = 0; mi < 2; mi++) {
#pragma unroll
        for (int half = 0; half < 2; half++) {
            const int r = m0 + warp_m * 32 + mi * 16 + (lane >> 2) + half * 8;
            const int b = r >> 10;
            const int s = r & 1023;
            const int base = (side == 0) ? s : (s + WW);
            const float* nrow = g_newin + ((size_t)b * SP2 + base) * DD;
#pragma unroll
            for (int ni = 0; ni < 8; ni++) {
                const int n = n0 + warp_n * 64 + ni * 8 + 2 * (lane & 3);
                float v0 = acc[mi][ni][half * 2 + 0] + bias[n];
                float v1 = acc[mi][ni][half * 2 + 1] + bias[n + 1];
#pragma unroll
                for (int j = 0; j <= WW; j++) {
                    float2 nv = *(const float2*)(nrow + (size_t)j * DD + n);
                    v0 = fmaf(wv[j], nv.x, v0);
                    v1 = fmaf(wv[j], nv.y, v1);
                }
                *(float2*)(C + (size_t)r * N + n) = make_float2(v0, v1);
            }
        }
    }
}

// ============ GEMM 3: highway layer with fused gate, side-batched ============
__global__ void __launch_bounds__(256, 2)
k_hwgemm(const float* __restrict__ lbias, const float* __restrict__ rbias,
         float* __restrict__ destBase, int destStride, int colOffStep,
         int l, int K)
{
    extern __shared__ float smf[];
    float* smA = smf;
    float* smB = smf + STAGES * STAGE_FLOATS;
    const int tid = threadIdx.x;
    const int wid = tid >> 5;
    const int lane = tid & 31;
    const int warp_m = wid & 3;
    const int warp_n = wid >> 2;
    const int m0 = blockIdx.y * 128;
    const int n0 = blockIdx.x * 64;
    const int side = blockIdx.z;
    const uint32_t sbA = smem_u32(smA);
    const uint32_t sbB = smem_u32(smB);
    const int ldrow = tid >> 1;
    const int ldseg = (tid & 1) * 8;
    const uint32_t daBase = sbA + (uint32_t)(ldrow * ROWSTRIDE + ldseg) * 4;
    const uint32_t dbBase = sbB + (uint32_t)(ldrow * ROWSTRIDE + ldseg) * 4;
    const int nch = K / KCH;
    const int M1 = BB * SS;

    const float* Xin = (l == 0 ? g_x : g_xb) + (size_t)side * M1 * DD;
    const float* Bt = g_hwWt + (size_t)(side * 2 + l) * DD2 * DD;
    const float* bias = (side ? rbias : lbias) + (size_t)l * DD2;
    float* dest = (destStride == DD) ? (destBase + (size_t)side * M1 * DD) : destBase;
    const int colOff = side * colOffStep;

    const float* agp = Xin + (size_t)(m0 + ldrow) * K + ldseg;
    const int brow_g = (ldrow < 64) ? (n0 + ldrow) : (512 + n0 + ldrow - 64);
    const float* bgp = Bt + (size_t)brow_g * K + ldseg;

    float accN[2][4][4];
    float accG[2][4][4];
#pragma unroll
    for (int mi = 0; mi < 2; mi++)
#pragma unroll
        for (int ni = 0; ni < 4; ni++)
#pragma unroll
            for (int j = 0; j < 4; j++) { accN[mi][ni][j] = 0.f; accG[mi][ni][j] = 0.f; }

    MAINLOOP(
#pragma unroll
        for (int s = 0; s < 4; s++) {
            const int cc = s * 8 + (lane & 3);
            uint32_t afr[2][4];
#pragma unroll
            for (int mi = 0; mi < 2; mi++) {
                const int r = warp_m * 32 + mi * 16 + (lane >> 2);
                afr[mi][0] = __float_as_uint(As[r * ROWSTRIDE + cc]);
                afr[mi][1] = __float_as_uint(As[(r + 8) * ROWSTRIDE + cc]);
                afr[mi][2] = __float_as_uint(As[r * ROWSTRIDE + cc + 4]);
                afr[mi][3] = __float_as_uint(As[(r + 8) * ROWSTRIDE + cc + 4]);
            }
            uint32_t bfrN[4][2];
            uint32_t bfrG[4][2];
#pragma unroll
            for (int ni = 0; ni < 4; ni++) {
                const int bn = warp_n * 32 + ni * 8 + (lane >> 2);
                bfrN[ni][0] = __float_as_uint(Bs[bn * ROWSTRIDE + cc]);
                bfrN[ni][1] = __float_as_uint(Bs[bn * ROWSTRIDE + cc + 4]);
                bfrG[ni][0] = __float_as_uint(Bs[(64 + bn) * ROWSTRIDE + cc]);
                bfrG[ni][1] = __float_as_uint(Bs[(64 + bn) * ROWSTRIDE + cc + 4]);
            }
#pragma unroll
            for (int mi = 0; mi < 2; mi++)
#pragma unroll
                for (int ni = 0; ni < 4; ni++) {
                    mma_tf32(accN[mi][ni], afr[mi], bfrN[ni]);
                    mma_tf32(accG[mi][ni], afr[mi], bfrG[ni]);
                }
        }
    )

#pragma unroll
    for (int mi = 0; mi < 2; mi++) {
#pragma unroll
        for (int half = 0; half < 2; half++) {
            const int r = m0 + warp_m * 32 + mi * 16 + (lane >> 2) + half * 8;
#pragma unroll
            for (int ni = 0; ni < 4; ni++) {
                const int n = n0 + warp_n * 32 + ni * 8 + 2 * (lane & 3);
                float nl0 = fmaxf(accN[mi][ni][half * 2 + 0] + bias[n], 0.f);
                float nl1 = fmaxf(accN[mi][ni][half * 2 + 1] + bias[n + 1], 0.f);
                float gv0 = accG[mi][ni][half * 2 + 0] + bias[512 + n];
                float gv1 = accG[mi][ni][half * 2 + 1] + bias[512 + n + 1];
                float g0 = 1.f / (1.f + __expf(-gv0));
                float g1 = 1.f / (1.f + __expf(-gv1));
                float2 xv = *(const float2*)(Xin + (size_t)r * DD + n);
                float o0 = g0 * xv.x + (1.f - g0) * nl0;
                float o1 = g1 * xv.y + (1.f - g1) * nl1;
                *(float2*)(dest + (size_t)r * destStride + colOff + n) = make_float2(o0, o1);
            }
        }
    }
}

// ---------------- transposes (tf32-round weights) ----------------
__global__ void k_transpose_attn(const float* __restrict__ lW, const float* __restrict__ rW)
{
    __shared__ float t[32][33];
    int z = blockIdx.z;
    int side = z >> 2, i = z & 3;
    const float* in = (side ? rW : lW) + (size_t)i * DD * DD;
    float* outb = (i < 3) ? (g_qkvWt + (size_t)(side * 1536 + i * 512) * DD)
                          : (g_opWt + (size_t)side * DD * DD);
    int rb = blockIdx.y * 32, cb = blockIdx.x * 32;
    t[threadIdx.y][threadIdx.x] = in[(size_t)(rb + threadIdx.y) * DD + cb + threadIdx.x];
    __syncthreads();
    float v = t[threadIdx.x][threadIdx.y];
    uint32_t r;
    asm("cvt.rna.tf32.f32 %0, %1;" : "=r"(r) : "f"(v));
    outb[(size_t)(cb + threadIdx.y) * DD + rb + threadIdx.x] = __uint_as_float(r);
}
__global__ void k_transpose_hw(const float* __restrict__ lhwW, const float* __restrict__ rhwW)
{
    __shared__ float t[32][33];
    int z = blockIdx.z;
    int side = z >> 1, l = z & 1;
    const float* in = (side ? rhwW : lhwW) + (size_t)l * DD * DD2;
    float* outb = g_hwWt + (size_t)(side * 2 + l) * DD2 * DD;
    int rb = blockIdx.y * 32, cb = blockIdx.x * 32;
    t[threadIdx.y][threadIdx.x] = in[(size_t)(rb + threadIdx.y) * DD2 + cb + threadIdx.x];
    __syncthreads();
    float v = t[threadIdx.x][threadIdx.y];
    uint32_t r;
    asm("cvt.rna.tf32.f32 %0, %1;" : "=r"(r) : "f"(v));
    outb[(size_t)(cb + threadIdx.y) * DD + rb + threadIdx.x] = __uint_as_float(r);
}
__global__ void k_pack_bias(const float* __restrict__ lb, const float* __restrict__ rb)
{
    int idx = blockIdx.x * blockDim.x + threadIdx.x;
    if (idx >= 2 * 3 * DD) return;
    int side = idx / 1536;
    int rem = idx % 1536;
    g_qkvb[idx] = (side ? rb : lb)[rem];
}

// ---------------- build padded input ----------------
__global__ void k_build_newin(const float* __restrict__ x,
                              const float* __restrict__ lpad,
                              const float* __restrict__ rpad)
{
    int idx = blockIdx.x * blockDim.x + threadIdx.x;
    int total = BB * SP2 * (DD / 4);
    if (idx >= total) return;
    int d4 = idx % (DD / 4);
    int s  = (idx / (DD / 4)) % SP2;
    int b  = idx / ((DD / 4) * SP2);

    float4 v;
    if (s < WW) {
        v = ((const float4*)(lpad + (size_t)s * DD))[d4];
    } else if (s < WW + SS) {
        v = ((const float4*)(x + ((size_t)b * SS + (s - WW)) * DD))[d4];
    } else {
        v = ((const float4*)(rpad + (size_t)(s - WW - SS) * DD))[d4];
    }
    ((float4*)(g_newin + ((size_t)b * SP2 + s) * DD))[d4] = v;
}

// ---------------- tiled banded attention (both sides) ----------------
__global__ void __launch_bounds__(256)
k_band_attn_t()
{
    extern __shared__ float sm[];
    float* sK = sm;                    // [AROWS][64]
    float* sV = sm + AROWS * 64;

    const int blk = blockIdx.x;
    const int sb = blk & 7;            // SS/SBLK = 8
    const int h = (blk >> 3) & 7;
    const int b = (blk >> 6) & 7;
    const int side = blk >> 9;

    const int s0 = sb * SBLK;
    const int j0 = s0 + WW - 9;        // first padded row in window (may be -1)
    const size_t qkvOff = (size_t)side * 1536 + (size_t)h * DKK;

    for (int idx = threadIdx.x; idx < AROWS * 16; idx += 256) {
        const int r = idx >> 4;
        const int d4 = idx & 15;
        int j = j0 + r;
        j = min(max(j, 0), SP2 - 1);
        const float* base = g_qkv + ((size_t)b * SP2 + j) * 3072 + qkvOff;
        ((float4*)(sK + r * 64))[d4] = ((const float4*)(base + 512))[d4];
        ((float4*)(sV + r * 64))[d4] = ((const float4*)(base + 1024))[d4];
    }
    __syncthreads();

    const int wid = threadIdx.x >> 5;
    const int lane = threadIdx.x & 31;

    for (int qq = 0; qq < 16; qq++) {
        const int sl = wid * 16 + qq;       // local query 0..127
        const int s = s0 + sl;
        const int i = s + WW;
        const float* qr = g_qkv + ((size_t)b * SP2 + i) * 3072 + qkvOff;
        const float q0 = qr[lane];
        const float q1 = qr[lane + 32];
        const int rbase = (side == 0) ? sl : (sl + 9);

        float sc[10];
#pragma unroll
        for (int t = 0; t < 10; t++) {
            const float* kr = sK + (rbase + t) * 64;
            float p = q0 * kr[lane] + q1 * kr[lane + 32];
#pragma unroll
            for (int o = 16; o > 0; o >>= 1) p += __shfl_xor_sync(0xffffffffu, p, o);
            const int j = (side == 0) ? (i - 9 + t) : (i + t);
            const bool valid = (side == 0) ? (j >= 0) : (j <= SP2 - 1);
            sc[t] = valid ? p * 0.125f : -1e9f;
        }

        float mx = -1e30f;
#pragma unroll
        for (int t = 0; t < 10; t++) mx = fmaxf(mx, sc[t]);
        float sum = 0.f;
#pragma unroll
        for (int t = 0; t < 10; t++) { sc[t] = __expf(sc[t] - mx); sum += sc[t]; }
        const float inv = 1.f / sum;

        float o0 = 0.f, o1 = 0.f;
#pragma unroll
        for (int t = 0; t < 10; t++) {
            const float* vr = sV + (rbase + t) * 64;
            const float p = sc[t] * inv;
            o0 = fmaf(p, vr[lane], o0);
            o1 = fmaf(p, vr[lane + 32], o1);
        }

        float* orow = g_attn + (size_t)side * BB * SS * DD + ((size_t)b * SS + s) * DD + h * DKK;
        orow[lane]      = o0;
        orow[lane + 32] = o1;
    }
}

// ---------------- launch ----------------
extern "C" void kernel_launch(void* const* d_in, const int* in_sizes, int n_in,
                              void* d_out, int out_size)
{
    const float* x     = (const float*)d_in[0];
    const float* lW    = (const float*)d_in[1];
    const float* lb    = (const float*)d_in[2];
    const float* rW    = (const float*)d_in[3];
    const float* rb    = (const float*)d_in[4];
    const float* lpad  = (const float*)d_in[5];
    const float* rpad  = (const float*)d_in[6];
    const float* lw    = (const float*)d_in[7];
    const float* rw    = (const float*)d_in[8];
    const float* lhwW  = (const float*)d_in[9];
    const float* lhwb  = (const float*)d_in[10];
    const float* rhwW  = (const float*)d_in[11];
    const float* rhwb  = (const float*)d_in[12];
    float* out = (float*)d_out;

    static bool attr_set = false;
    if (!attr_set) {
        cudaFuncSetAttribute(k_tgemm, cudaFuncAttributeMaxDynamicSharedMemorySize, SMEM_SZ);
        cudaFuncSetAttribute(k_opgemm, cudaFuncAttributeMaxDynamicSharedMemorySize, SMEM_SZ);
        cudaFuncSetAttribute(k_hwgemm, cudaFuncAttributeMaxDynamicSharedMemorySize, SMEM_SZ);
        cudaFuncSetAttribute(k_band_attn_t, cudaFuncAttributeMaxDynamicSharedMemorySize, ATTN_SMEM);
        attr_set = true;
    }

    float *p_newin, *p_qkv, *p_qkvWt, *p_qkvb, *p_xb;
    cudaGetSymbolAddress((void**)&p_newin, g_newin);
    cudaGetSymbolAddress((void**)&p_qkv, g_qkv);
    cudaGetSymbolAddress((void**)&p_qkvWt, g_qkvWt);
    cudaGetSymbolAddress((void**)&p_qkvb, g_qkvb);
    cudaGetSymbolAddress((void**)&p_xb, g_xb);

    // weight prep
    {
        dim3 blk(32, 32);
        k_transpose_attn<<<dim3(16, 16, 8), blk>>>(lW, rW);
        k_transpose_hw<<<dim3(32, 16, 4), blk>>>(lhwW, rhwW);
        k_pack_bias<<<(3072 + 255) / 256, 256>>>(lb, rb);
    }
    // padded input
    {
        int total = BB * SP2 * (DD / 4);
        k_build_newin<<<(total + 255) / 256, 256>>>(x, lpad, rpad);
    }

    const int M2 = BB * SP2;   // 8320
    const int M1 = BB * SS;    // 8192

    // combined QKV (both sides): M2 x 3072
    k_tgemm<<<dim3(3072 / 128, M2 / 128), 256, SMEM_SZ>>>(p_newin, p_qkvWt, p_qkvb, p_qkv,
                                                          M2, 3072, DD);
    // tiled banded attention (both sides)
    k_band_attn_t<<<1024, 256, ATTN_SMEM>>>();

    // out-proj + fused addrel, both sides
    k_opgemm<<<dim3(DD / 128, M1 / 128, 2), 256, SMEM_SZ>>>(lw, rw, lb + 3 * DD, rb + 3 * DD,
                                                            M1, DD, DD);
    // highway layer 1 (both sides): g_x -> g_xb
    k_hwgemm<<<dim3(DD / 64, M1 / 128, 2), 256, SMEM_SZ>>>(lhwb, rhwb, p_xb, DD, 0, 0, DD);
    // highway layer 2 (both sides): g_xb -> out
    k_hwgemm<<<dim3(DD / 64, M1 / 128, 2), 256, SMEM_SZ>>>(lhwb, rhwb, out, DD2, DD, 1, DD);
}

// round 16
// speedup vs baseline: 1.3033x; 1.3033x over previous
#include <cuda_runtime.h>
#include <cuda_fp16.h>
#include <cstdint>
#include <math.h>

#define BB 8
#define SS 1024
#define DD 512
#define HH 8
#define WW 8
#define DKK 64
#define SP2 1040   // S + 2*WIDTH
#define DD2 1024   // 2*D

// fp16 GEMM tiling: STAGES=3 double-barrier (R9-proven shape), KCH=32 halves
#define STAGES 3
#define KCH 32                               // half elements per k-chunk
#define RSW 20                               // 32-bit words per smem row (16 data + 4 pad)
#define STAGE_WORDS (128 * RSW)
#define STAGE_BYTES (STAGE_WORDS * 4)        // 10240
#define SMEM_SZ (2 * STAGES * STAGE_BYTES)   // 61440 B (x2 CTAs/SM fits)

// attention tiling
#define SBLK 128
#define AROWS (SBLK + 18)                    // 146
#define ATTN_SMEM (2 * AROWS * 64 * 4)       // 74752 B

// ---------------- scratch ----------------
__device__ float  g_newin[(size_t)BB * SP2 * DD];
__device__ __half g_newinh[(size_t)BB * SP2 * DD];
__device__ float  g_qkv[(size_t)BB * SP2 * 3072];   // [row][side*1536 + {q,k,v}*512 + d]
__device__ __half g_attnh[2 * (size_t)BB * SS * DD];
__device__ float  g_x[2 * (size_t)BB * SS * DD];
__device__ __half g_xh[2 * (size_t)BB * SS * DD];
__device__ float  g_xb[2 * (size_t)BB * SS * DD];
__device__ __half g_xbh[2 * (size_t)BB * SS * DD];
// transposed weights [N][K], fp16
__device__ __half g_qkvWh[2 * 3 * DD * DD];
__device__ __half g_opWh[2 * DD * DD];
__device__ __half g_hwWh[2 * 2 * DD2 * DD];
__device__ float  g_qkvb[2 * 3 * DD];

// ---------------- helpers ----------------
__device__ __forceinline__ uint32_t smem_u32(const void* p) {
    uint32_t a;
    asm("{ .reg .u64 t; cvta.to.shared.u64 t, %1; cvt.u32.u64 %0, t; }" : "=r"(a) : "l"(p));
    return a;
}
__device__ __forceinline__ void cpa16(uint32_t dst, const void* src) {
    asm volatile("cp.async.cg.shared.global [%0], [%1], 16;" :: "r"(dst), "l"(src));
}
__device__ __forceinline__ void mma_f16(float* d, const uint32_t* a, const uint32_t* b) {
    asm volatile(
        "mma.sync.aligned.m16n8k16.row.col.f32.f16.f16.f32 "
        "{%0,%1,%2,%3}, {%4,%5,%6,%7}, {%8,%9}, {%0,%1,%2,%3};"
        : "+f"(d[0]), "+f"(d[1]), "+f"(d[2]), "+f"(d[3])
        : "r"(a[0]), "r"(a[1]), "r"(a[2]), "r"(a[3]), "r"(b[0]), "r"(b[1]));
}

#define GEMM_PRE()                                                        \
    extern __shared__ uint32_t smw[];                                     \
    uint32_t* smA = smw;                                                  \
    uint32_t* smB = smw + STAGES * STAGE_WORDS;                           \
    const int tid = threadIdx.x;                                          \
    const int wid = tid >> 5;                                             \
    const int lane = tid & 31;                                            \
    const int warp_m = wid & 3;                                           \
    const int warp_n = wid >> 2;                                          \
    const int m0 = blockIdx.y * 128;                                      \
    const uint32_t sbA = smem_u32(smA);                                   \
    const uint32_t sbB = smem_u32(smB);                                   \
    const int ldrow = tid & 127;                                          \
    const bool ldB = tid >= 128;                                          \
    const uint32_t dBase = (ldB ? sbB : sbA) + (uint32_t)ldrow * (RSW * 4);

// one row (A or B) per thread per chunk: 32 halves = 4 x 16B
#define ISSUE(c) do {                                                   \
        int _sl = (c) % STAGES;                                         \
        uint32_t _d = dBase + _sl * STAGE_BYTES;                        \
        const __half* _g = gp + (size_t)(c) * KCH;                      \
        cpa16(_d,      _g);                                             \
        cpa16(_d + 16, _g + 8);                                         \
        cpa16(_d + 32, _g + 16);                                        \
        cpa16(_d + 48, _g + 24);                                        \
        asm volatile("cp.async.commit_group;" ::: "memory");            \
    } while (0)

// R9-proven double-barrier mainloop (STAGES=3, prefetch distance 2)
#define MAINLOOP(...)                                                     \
    ISSUE(0); ISSUE(1);                                                   \
    for (int c = 0; c < nch; c++) {                                       \
        if (c + 2 < nch) { ISSUE(c + 2); }                                \
        else { asm volatile("cp.async.commit_group;" ::: "memory"); }     \
        asm volatile("cp.async.wait_group 2;" ::: "memory");              \
        __syncthreads();                                                  \
        const int sl = c % STAGES;                                        \
        const uint32_t* As = smA + sl * STAGE_WORDS;                      \
        const uint32_t* Bs = smB + sl * STAGE_WORDS;                      \
        __VA_ARGS__                                                       \
        __syncthreads();                                                  \
    }

// ============ GEMM 1: generic C = A @ Bt^T + bias (128x128 tile, fp16 in) ============
__global__ void __launch_bounds__(256, 2)
k_tgemm(const __half* __restrict__ A, const __half* __restrict__ Bt,
        const float* __restrict__ bias, float* __restrict__ C,
        int M, int N, int K)
{
    GEMM_PRE();
    const int n0 = blockIdx.x * 128;
    const int nch = K / KCH;
    const __half* agp = A  + (size_t)(m0 + ldrow) * K;
    const __half* bgp = Bt + (size_t)(n0 + ldrow) * K;
    const __half* gp = ldB ? bgp : agp;

    float acc[2][8][4];
#pragma unroll
    for (int mi = 0; mi < 2; mi++)
#pragma unroll
        for (int ni = 0; ni < 8; ni++)
#pragma unroll
            for (int j = 0; j < 4; j++) acc[mi][ni][j] = 0.f;

    MAINLOOP(
#pragma unroll
        for (int s = 0; s < 2; s++) {
            const int kw = s * 8 + (lane & 3);
            uint32_t afr[2][4];
#pragma unroll
            for (int mi = 0; mi < 2; mi++) {
                const int r = warp_m * 32 + mi * 16 + (lane >> 2);
                afr[mi][0] = As[r * RSW + kw];
                afr[mi][1] = As[(r + 8) * RSW + kw];
                afr[mi][2] = As[r * RSW + kw + 4];
                afr[mi][3] = As[(r + 8) * RSW + kw + 4];
            }
            uint32_t bfr[8][2];
#pragma unroll
            for (int ni = 0; ni < 8; ni++) {
                const int n = warp_n * 64 + ni * 8 + (lane >> 2);
                bfr[ni][0] = Bs[n * RSW + kw];
                bfr[ni][1] = Bs[n * RSW + kw + 4];
            }
#pragma unroll
            for (int mi = 0; mi < 2; mi++)
#pragma unroll
                for (int ni = 0; ni < 8; ni++)
                    mma_f16(acc[mi][ni], afr[mi], bfr[ni]);
        }
    )

#pragma unroll
    for (int mi = 0; mi < 2; mi++) {
        const int r = m0 + warp_m * 32 + mi * 16 + (lane >> 2);
#pragma unroll
        for (int ni = 0; ni < 8; ni++) {
            const int n = n0 + warp_n * 64 + ni * 8 + 2 * (lane & 3);
            const float b0 = bias[n], b1 = bias[n + 1];
            *(float2*)(C + (size_t)r * N + n) = make_float2(acc[mi][ni][0] + b0, acc[mi][ni][1] + b1);
            *(float2*)(C + (size_t)(r + 8) * N + n) = make_float2(acc[mi][ni][2] + b0, acc[mi][ni][3] + b1);
        }
    }
}

// ============ GEMM 2: out-proj + fused relative add, side-batched ============
__global__ void __launch_bounds__(256, 2)
k_opgemm(const float* __restrict__ lw, const float* __restrict__ rw,
         const float* __restrict__ lb3, const float* __restrict__ rb3,
         int M, int N, int K)
{
    GEMM_PRE();
    const int n0 = blockIdx.x * 128;
    const int side = blockIdx.z;
    const int nch = K / KCH;
    const __half* A  = g_attnh + (size_t)side * M * K;
    const __half* Bt = g_opWh + (size_t)side * DD * DD;
    const float* bias = (side ? rb3 : lb3);
    const float* relw = side ? rw : lw;
    float*  C  = g_x  + (size_t)side * M * N;
    __half* Ch = g_xh + (size_t)side * M * N;

    const __half* agp = A  + (size_t)(m0 + ldrow) * K;
    const __half* bgp = Bt + (size_t)(n0 + ldrow) * K;
    const __half* gp = ldB ? bgp : agp;

    float acc[2][8][4];
#pragma unroll
    for (int mi = 0; mi < 2; mi++)
#pragma unroll
        for (int ni = 0; ni < 8; ni++)
#pragma unroll
            for (int j = 0; j < 4; j++) acc[mi][ni][j] = 0.f;

    MAINLOOP(
#pragma unroll
        for (int s = 0; s < 2; s++) {
            const int kw = s * 8 + (lane & 3);
            uint32_t afr[2][4];
#pragma unroll
            for (int mi = 0; mi < 2; mi++) {
                const int r = warp_m * 32 + mi * 16 + (lane >> 2);
                afr[mi][0] = As[r * RSW + kw];
                afr[mi][1] = As[(r + 8) * RSW + kw];
                afr[mi][2] = As[r * RSW + kw + 4];
                afr[mi][3] = As[(r + 8) * RSW + kw + 4];
            }
            uint32_t bfr[8][2];
#pragma unroll
            for (int ni = 0; ni < 8; ni++) {
                const int n = warp_n * 64 + ni * 8 + (lane >> 2);
                bfr[ni][0] = Bs[n * RSW + kw];
                bfr[ni][1] = Bs[n * RSW + kw + 4];
            }
#pragma unroll
            for (int mi = 0; mi < 2; mi++)
#pragma unroll
                for (int ni = 0; ni < 8; ni++)
                    mma_f16(acc[mi][ni], afr[mi], bfr[ni]);
        }
    )

    float wv[WW + 1];
#pragma unroll
    for (int j = 0; j <= WW; j++) wv[j] = relw[j];

#pragma unroll
    for (int mi = 0; mi < 2; mi++) {
#pragma unroll
        for (int half = 0; half < 2; half++) {
            const int r = m0 + warp_m * 32 + mi * 16 + (lane >> 2) + half * 8;
            const int b = r >> 10;
            const int s = r & 1023;
            const int base = (side == 0) ? s : (s + WW);
            const float* nrow = g_newin + ((size_t)b * SP2 + base) * DD;
#pragma unroll
            for (int ni = 0; ni < 8; ni++) {
                const int n = n0 + warp_n * 64 + ni * 8 + 2 * (lane & 3);
                float v0 = acc[mi][ni][half * 2 + 0] + bias[n];
                float v1 = acc[mi][ni][half * 2 + 1] + bias[n + 1];
#pragma unroll
                for (int j = 0; j <= WW; j++) {
                    float2 nv = *(const float2*)(nrow + (size_t)j * DD + n);
                    v0 = fmaf(wv[j], nv.x, v0);
                    v1 = fmaf(wv[j], nv.y, v1);
                }
                *(float2*)(C + (size_t)r * N + n) = make_float2(v0, v1);
                *(__half2*)(Ch + (size_t)r * N + n) = __floats2half2_rn(v0, v1);
            }
        }
    }
}

// ============ GEMM 3: highway layer with fused gate, side-batched ============
__global__ void __launch_bounds__(256, 2)
k_hwgemm(const float* __restrict__ lbias, const float* __restrict__ rbias,
         float* __restrict__ outPtr, int l, int K)
{
    extern __shared__ uint32_t smw[];
    uint32_t* smA = smw;
    uint32_t* smB = smw + STAGES * STAGE_WORDS;
    const int tid = threadIdx.x;
    const int wid = tid >> 5;
    const int lane = tid & 31;
    const int warp_m = wid & 3;
    const int warp_n = wid >> 2;
    const int m0 = blockIdx.y * 128;
    const int n0 = blockIdx.x * 64;
    const int side = blockIdx.z;
    const uint32_t sbA = smem_u32(smA);
    const uint32_t sbB = smem_u32(smB);
    const int ldrow = tid & 127;
    const bool ldB = tid >= 128;
    const uint32_t dBase = (ldB ? sbB : sbA) + (uint32_t)ldrow * (RSW * 4);
    const int nch = K / KCH;
    const int M1 = BB * SS;

    const __half* XinH = (l == 0 ? g_xh : g_xbh) + (size_t)side * M1 * DD;
    const float*  Xold = (l == 0 ? g_x  : g_xb)  + (size_t)side * M1 * DD;
    const __half* Bt = g_hwWh + (size_t)(side * 2 + l) * DD2 * DD;
    const float* bias = (side ? rbias : lbias) + (size_t)l * DD2;
    // l==0: dest = g_xb[side] (stride DD) + half copy g_xbh; l==1: dest = out, stride DD2, colOff side*DD
    float* dest = (l == 0) ? (g_xb + (size_t)side * M1 * DD) : outPtr;
    __half* destH = (l == 0) ? (g_xbh + (size_t)side * M1 * DD) : (__half*)0;
    const int destStride = (l == 0) ? DD : DD2;
    const int colOff = (l == 0) ? 0 : side * DD;

    const __half* agp = XinH + (size_t)(m0 + ldrow) * K;
    const int brow_g = (ldrow < 64) ? (n0 + ldrow) : (512 + n0 + ldrow - 64);
    const __half* bgp = Bt + (size_t)brow_g * K;
    const __half* gp = ldB ? bgp : agp;

    float accN[2][4][4];
    float accG[2][4][4];
#pragma unroll
    for (int mi = 0; mi < 2; mi++)
#pragma unroll
        for (int ni = 0; ni < 4; ni++)
#pragma unroll
            for (int j = 0; j < 4; j++) { accN[mi][ni][j] = 0.f; accG[mi][ni][j] = 0.f; }

    MAINLOOP(
#pragma unroll
        for (int s = 0; s < 2; s++) {
            const int kw = s * 8 + (lane & 3);
            uint32_t afr[2][4];
#pragma unroll
            for (int mi = 0; mi < 2; mi++) {
                const int r = warp_m * 32 + mi * 16 + (lane >> 2);
                afr[mi][0] = As[r * RSW + kw];
                afr[mi][1] = As[(r + 8) * RSW + kw];
                afr[mi][2] = As[r * RSW + kw + 4];
                afr[mi][3] = As[(r + 8) * RSW + kw + 4];
            }
            uint32_t bfrN[4][2];
            uint32_t bfrG[4][2];
#pragma unroll
            for (int ni = 0; ni < 4; ni++) {
                const int bn = warp_n * 32 + ni * 8 + (lane >> 2);
                bfrN[ni][0] = Bs[bn * RSW + kw];
                bfrN[ni][1] = Bs[bn * RSW + kw + 4];
                bfrG[ni][0] = Bs[(64 + bn) * RSW + kw];
                bfrG[ni][1] = Bs[(64 + bn) * RSW + kw + 4];
            }
#pragma unroll
            for (int mi = 0; mi < 2; mi++)
#pragma unroll
                for (int ni = 0; ni < 4; ni++) {
                    mma_f16(accN[mi][ni], afr[mi], bfrN[ni]);
                    mma_f16(accG[mi][ni], afr[mi], bfrG[ni]);
                }
        }
    )

#pragma unroll
    for (int mi = 0; mi < 2; mi++) {
#pragma unroll
        for (int half = 0; half < 2; half++) {
            const int r = m0 + warp_m * 32 + mi * 16 + (lane >> 2) + half * 8;
#pragma unroll
            for (int ni = 0; ni < 4; ni++) {
                const int n = n0 + warp_n * 32 + ni * 8 + 2 * (lane & 3);
                float nl0 = fmaxf(accN[mi][ni][half * 2 + 0] + bias[n], 0.f);
                float nl1 = fmaxf(accN[mi][ni][half * 2 + 1] + bias[n + 1], 0.f);
                float gv0 = accG[mi][ni][half * 2 + 0] + bias[512 + n];
                float gv1 = accG[mi][ni][half * 2 + 1] + bias[512 + n + 1];
                float g0 = 1.f / (1.f + __expf(-gv0));
                float g1 = 1.f / (1.f + __expf(-gv1));
                float2 xv = *(const float2*)(Xold + (size_t)r * DD + n);
                float o0 = g0 * xv.x + (1.f - g0) * nl0;
                float o1 = g1 * xv.y + (1.f - g1) * nl1;
                *(float2*)(dest + (size_t)r * destStride + colOff + n) = make_float2(o0, o1);
                if (destH)
                    *(__half2*)(destH + (size_t)r * DD + n) = __floats2half2_rn(o0, o1);
            }
        }
    }
}

// ---------------- transposes (fp16 weights) ----------------
__global__ void k_transpose_attn(const float* __restrict__ lW, const float* __restrict__ rW)
{
    __shared__ float t[32][33];
    int z = blockIdx.z;
    int side = z >> 2, i = z & 3;
    const float* in = (side ? rW : lW) + (size_t)i * DD * DD;
    __half* outb = (i < 3) ? (g_qkvWh + (size_t)(side * 1536 + i * 512) * DD)
                           : (g_opWh + (size_t)side * DD * DD);
    int rb = blockIdx.y * 32, cb = blockIdx.x * 32;
    t[threadIdx.y][threadIdx.x] = in[(size_t)(rb + threadIdx.y) * DD + cb + threadIdx.x];
    __syncthreads();
    outb[(size_t)(cb + threadIdx.y) * DD + rb + threadIdx.x] =
        __float2half_rn(t[threadIdx.x][threadIdx.y]);
}
__global__ void k_transpose_hw(const float* __restrict__ lhwW, const float* __restrict__ rhwW)
{
    __shared__ float t[32][33];
    int z = blockIdx.z;
    int side = z >> 1, l = z & 1;
    const float* in = (side ? rhwW : lhwW) + (size_t)l * DD * DD2;
    __half* outb = g_hwWh + (size_t)(side * 2 + l) * DD2 * DD;
    int rb = blockIdx.y * 32, cb = blockIdx.x * 32;
    t[threadIdx.y][threadIdx.x] = in[(size_t)(rb + threadIdx.y) * DD2 + cb + threadIdx.x];
    __syncthreads();
    outb[(size_t)(cb + threadIdx.y) * DD + rb + threadIdx.x] =
        __float2half_rn(t[threadIdx.x][threadIdx.y]);
}
__global__ void k_pack_bias(const float* __restrict__ lb, const float* __restrict__ rb)
{
    int idx = blockIdx.x * blockDim.x + threadIdx.x;
    if (idx >= 2 * 3 * DD) return;
    int side = idx / 1536;
    int rem = idx % 1536;
    g_qkvb[idx] = (side ? rb : lb)[rem];
}

// ---------------- build padded input (fp32 + fp16) ----------------
__global__ void k_build_newin(const float* __restrict__ x,
                              const float* __restrict__ lpad,
                              const float* __restrict__ rpad)
{
    int idx = blockIdx.x * blockDim.x + threadIdx.x;
    int total = BB * SP2 * (DD / 4);
    if (idx >= total) return;
    int d4 = idx % (DD / 4);
    int s  = (idx / (DD / 4)) % SP2;
    int b  = idx / ((DD / 4) * SP2);

    float4 v;
    if (s < WW) {
        v = ((const float4*)(lpad + (size_t)s * DD))[d4];
    } else if (s < WW + SS) {
        v = ((const float4*)(x + ((size_t)b * SS + (s - WW)) * DD))[d4];
    } else {
        v = ((const float4*)(rpad + (size_t)(s - WW - SS) * DD))[d4];
    }
    ((float4*)(g_newin + ((size_t)b * SP2 + s) * DD))[d4] = v;
    __half2* hp = (__half2*)(g_newinh + ((size_t)b * SP2 + s) * DD) + 2 * d4;
    hp[0] = __floats2half2_rn(v.x, v.y);
    hp[1] = __floats2half2_rn(v.z, v.w);
}

// ---------------- tiled banded attention (both sides), fp16 output ----------------
__global__ void __launch_bounds__(256)
k_band_attn_t()
{
    extern __shared__ float sm[];
    float* sK = sm;                    // [AROWS][64]
    float* sV = sm + AROWS * 64;

    const int blk = blockIdx.x;
    const int sb = blk & 7;            // SS/SBLK = 8
    const int h = (blk >> 3) & 7;
    const int b = (blk >> 6) & 7;
    const int side = blk >> 9;

    const int s0 = sb * SBLK;
    const int j0 = s0 + WW - 9;        // first padded row in window (may be -1)
    const size_t qkvOff = (size_t)side * 1536 + (size_t)h * DKK;

    for (int idx = threadIdx.x; idx < AROWS * 16; idx += 256) {
        const int r = idx >> 4;
        const int d4 = idx & 15;
        int j = j0 + r;
        j = min(max(j, 0), SP2 - 1);
        const float* base = g_qkv + ((size_t)b * SP2 + j) * 3072 + qkvOff;
        ((float4*)(sK + r * 64))[d4] = ((const float4*)(base + 512))[d4];
        ((float4*)(sV + r * 64))[d4] = ((const float4*)(base + 1024))[d4];
    }
    __syncthreads();

    const int wid = threadIdx.x >> 5;
    const int lane = threadIdx.x & 31;

    for (int qq = 0; qq < 16; qq++) {
        const int sl = wid * 16 + qq;       // local query 0..127
        const int s = s0 + sl;
        const int i = s + WW;
        const float* qr = g_qkv + ((size_t)b * SP2 + i) * 3072 + qkvOff;
        const float q0 = qr[lane];
        const float q1 = qr[lane + 32];
        const int rbase = (side == 0) ? sl : (sl + 9);

        float sc[10];
#pragma unroll
        for (int t = 0; t < 10; t++) {
            const float* kr = sK + (rbase + t) * 64;
            float p = q0 * kr[lane] + q1 * kr[lane + 32];
#pragma unroll
            for (int o = 16; o > 0; o >>= 1) p += __shfl_xor_sync(0xffffffffu, p, o);
            const int j = (side == 0) ? (i - 9 + t) : (i + t);
            const bool valid = (side == 0) ? (j >= 0) : (j <= SP2 - 1);
            sc[t] = valid ? p * 0.125f : -1e9f;
        }

        float mx = -1e30f;
#pragma unroll
        for (int t = 0; t < 10; t++) mx = fmaxf(mx, sc[t]);
        float sum = 0.f;
#pragma unroll
        for (int t = 0; t < 10; t++) { sc[t] = __expf(sc[t] - mx); sum += sc[t]; }
        const float inv = 1.f / sum;

        float o0 = 0.f, o1 = 0.f;
#pragma unroll
        for (int t = 0; t < 10; t++) {
            const float* vr = sV + (rbase + t) * 64;
            const float p = sc[t] * inv;
            o0 = fmaf(p, vr[lane], o0);
            o1 = fmaf(p, vr[lane + 32], o1);
        }

        __half* orow = g_attnh + (size_t)side * BB * SS * DD + ((size_t)b * SS + s) * DD + h * DKK;
        orow[lane]      = __float2half_rn(o0);
        orow[lane + 32] = __float2half_rn(o1);
    }
}

// ---------------- launch ----------------
extern "C" void kernel_launch(void* const* d_in, const int* in_sizes, int n_in,
                              void* d_out, int out_size)
{
    const float* x     = (const float*)d_in[0];
    const float* lW    = (const float*)d_in[1];
    const float* lb    = (const float*)d_in[2];
    const float* rW    = (const float*)d_in[3];
    const float* rb    = (const float*)d_in[4];
    const float* lpad  = (const float*)d_in[5];
    const float* rpad  = (const float*)d_in[6];
    const float* lw    = (const float*)d_in[7];
    const float* rw    = (const float*)d_in[8];
    const float* lhwW  = (const float*)d_in[9];
    const float* lhwb  = (const float*)d_in[10];
    const float* rhwW  = (const float*)d_in[11];
    const float* rhwb  = (const float*)d_in[12];
    float* out = (float*)d_out;

    static bool attr_set = false;
    if (!attr_set) {
        cudaFuncSetAttribute(k_tgemm, cudaFuncAttributeMaxDynamicSharedMemorySize, SMEM_SZ);
        cudaFuncSetAttribute(k_opgemm, cudaFuncAttributeMaxDynamicSharedMemorySize, SMEM_SZ);
        cudaFuncSetAttribute(k_hwgemm, cudaFuncAttributeMaxDynamicSharedMemorySize, SMEM_SZ);
        cudaFuncSetAttribute(k_band_attn_t, cudaFuncAttributeMaxDynamicSharedMemorySize, ATTN_SMEM);
        attr_set = true;
    }

    float *p_qkv, *p_qkvb;
    __half *p_newinh, *p_qkvWh;
    cudaGetSymbolAddress((void**)&p_qkv, g_qkv);
    cudaGetSymbolAddress((void**)&p_qkvb, g_qkvb);
    cudaGetSymbolAddress((void**)&p_newinh, g_newinh);
    cudaGetSymbolAddress((void**)&p_qkvWh, g_qkvWh);

    // weight prep
    {
        dim3 blk(32, 32);
        k_transpose_attn<<<dim3(16, 16, 8), blk>>>(lW, rW);
        k_transpose_hw<<<dim3(32, 16, 4), blk>>>(lhwW, rhwW);
        k_pack_bias<<<(3072 + 255) / 256, 256>>>(lb, rb);
    }
    // padded input (fp32 + fp16)
    {
        int total = BB * SP2 * (DD / 4);
        k_build_newin<<<(total + 255) / 256, 256>>>(x, lpad, rpad);
    }

    const int M2 = BB * SP2;   // 8320
    const int M1 = BB * SS;    // 8192

    // combined QKV (both sides): M2 x 3072, fp16 inputs -> fp32 qkv
    k_tgemm<<<dim3(3072 / 128, M2 / 128), 256, SMEM_SZ>>>(p_newinh, p_qkvWh, p_qkvb, p_qkv,
                                                          M2, 3072, DD);
    // tiled banded attention (both sides) -> fp16 attn
    k_band_attn_t<<<1024, 256, ATTN_SMEM>>>();

    // out-proj + fused addrel, both sides -> g_x (fp32) + g_xh (fp16)
    k_opgemm<<<dim3(DD / 128, M1 / 128, 2), 256, SMEM_SZ>>>(lw, rw, lb + 3 * DD, rb + 3 * DD,
                                                            M1, DD, DD);
    // highway layer 1 (both sides): g_xh -> g_xb + g_xbh
    k_hwgemm<<<dim3(DD / 64, M1 / 128, 2), 256, SMEM_SZ>>>(lhwb, rhwb, out, 0, DD);
    // highway layer 2 (both sides): g_xbh -> out
    k_hwgemm<<<dim3(DD / 64, M1 / 128, 2), 256, SMEM_SZ>>>(lhwb, rhwb, out, 1, DD);
}